// round 14
// baseline (speedup 1.0000x reference)
#include <cuda_runtime.h>
#include <math.h>
#include <stdint.h>

#define FH 200
#define FW 200
#define NPIX 40000
#define ICH 256
#define NA 9
#define NH 45
#define NHP 23                      // padded head pairs (46 heads, last is zero)
#define NSC 360000
#define TOPK 2000
#define OUTK 1000
#define BBOX_CLIP_F 4.135166556742356f

// ---------------- persistent scratch (device globals; no allocation) --------
__device__ float g_x[ICH * NPIX];           // conv+relu output [oc][pix]
__device__ float g_wt[ICH * 9 * ICH];       // transposed conv weights [ic][tap][oc]
__device__ unsigned g_key[NSC];             // sigmoid score bits (monotone key)
__device__ float g_delta[NSC * 4];          // reg deltas [idx][4]
__device__ unsigned g_hist1[65536];
__device__ unsigned g_hist2[65536];
__device__ unsigned g_sel[8];               // 0:B 1:cntAboveB 2:T 3:cntGreater 5:ctrG 6:ctrE
__device__ unsigned g_candG[2048];
__device__ unsigned g_candE[2048];
__device__ unsigned long long g_top[TOPK];  // sorted (key<<32 | ~idx), descending
__device__ float g_bx[TOPK * 4];            // partitioned boxes (valid first)
__device__ float g_sc[TOPK];                // partitioned scores (-1 invalid)
__device__ unsigned long long g_mask[TOPK * 32];

// ---------------------------------------------------------------- init ------
__global__ void k_init(float* out) {
    int i = blockIdx.x * blockDim.x + threadIdx.x;
    if (i < 65536) { g_hist1[i] = 0u; g_hist2[i] = 0u; }
    if (i < 8) g_sel[i] = 0u;
    if (i < 5000) out[i] = 0.f;
}

// conv_w [oc][ic][ky][kx] -> g_wt [ic][tap][oc]
__global__ void k_wt(const float* __restrict__ w) {
    int i = blockIdx.x * blockDim.x + threadIdx.x;
    if (i >= ICH * 9 * ICH) return;
    int ic = i / (9 * ICH);
    int tap = (i / ICH) % 9;
    int oc = i % ICH;
    g_wt[i] = w[(oc * ICH + ic) * 9 + tap];
}

// nop: aligns k_conv to profiled stream launch index 3
__global__ void k_nop() {}

// ------------------------------------------------------------ conv 3x3 ------
// tile: 64 oc x (8 rows x 16 cols). grid (13,25,4), 256 threads.
// f32x2 FMA over oc-pairs. Inner nesting p-outer/j2-inner so consecutive
// FFMA2s reuse the xx operand (RF-bank relief). Weight prefetch addressing
// is linear: g_wt flat copy index i=tid+256k maps to off = ch*18432 +
// (tid>>6)*256 + ocB + (tid&63) + 1024k.  Bit-exact vs round-10/11 kernels.
__global__ __launch_bounds__(256, 2) void k_conv(const float* __restrict__ feat,
                                                 const float* __restrict__ bias) {
    __shared__ float Ws[8 * 9 * 64];     // [icl][tap][oc']  18432 B
    __shared__ float2 Xs[8 * 190];       // [icl][rr(10) x 19] duplicated

    const int tid = threadIdx.x;
    const int og = tid >> 5;             // warp id -> oc sub-group (8 oc)
    const int pg = tid & 31;
    const int r  = pg >> 2;              // row in tile 0..7
    const int c0 = (pg & 3) << 2;        // col base 0,4,8,12
    const int xB = blockIdx.x * 16;
    const int yB = blockIdx.y * 8;
    const int ocB = blockIdx.z * 64;

    unsigned long long acc2[4][4];       // [oc-pair j2][pixel p]
#pragma unroll
    for (int j2 = 0; j2 < 4; j2++)
#pragma unroll
        for (int p = 0; p < 4; p++) acc2[j2][p] = 0ull;

    // ---- prefetch addressing ----
    const int wbase = (tid >> 6) * 256 + ocB + (tid & 63);  // + ch*18432 + k*1024
    int xGOff[6], xSOff[6];
    unsigned okm = 0u;                   // bit k: in-range & in-bounds
#pragma unroll
    for (int k = 0; k < 6; k++) {
        int i = tid + k * 256;
        bool xin = (i < 1440);
        int icl = i / 180;
        int rem = i - icl * 180;
        int rr = rem / 18;
        int cc = rem - rr * 18;
        int gy = yB - 1 + rr;
        int gx = xB - 1 + cc;
        bool inb = xin && gy >= 0 && gy < FH && gx >= 0 && gx < FW;
        if (inb) okm |= (1u << k);
        xGOff[k] = inb ? (icl * NPIX + gy * FW + gx) : 0;
        xSOff[k] = xin ? (icl * 190 + rr * 19 + cc) : 0;
    }
    const bool xin5 = (tid < 1440 - 5 * 256);

    float wbuf[18], xbuf[6];
#pragma unroll
    for (int k = 0; k < 18; k++) wbuf[k] = g_wt[wbase + k * 1024];
#pragma unroll
    for (int k = 0; k < 6; k++) xbuf[k] = (okm >> k & 1u) ? feat[xGOff[k]] : 0.f;

    for (int ch = 0; ch < 32; ch++) {
        __syncthreads();
#pragma unroll
        for (int k = 0; k < 18; k++) Ws[tid + k * 256] = wbuf[k];
#pragma unroll
        for (int k = 0; k < 6; k++)
            if (k < 5 || xin5) Xs[xSOff[k]] = make_float2(xbuf[k], xbuf[k]);
        __syncthreads();
        if (ch < 31) {
            const int wb = (ch + 1) * (8 * 9 * ICH) + wbase;
            const int xb = (ch + 1) * (8 * NPIX);
#pragma unroll
            for (int k = 0; k < 18; k++) wbuf[k] = g_wt[wb + k * 1024];
#pragma unroll
            for (int k = 0; k < 6; k++)
                xbuf[k] = (okm >> k & 1u) ? feat[xGOff[k] + xb] : 0.f;
        }

#pragma unroll
        for (int icl = 0; icl < 8; icl++) {
#pragma unroll
            for (int ky = 0; ky < 3; ky++) {
                unsigned long long xx[6];
                const unsigned long long* xrow = reinterpret_cast<const unsigned long long*>(
                    &Xs[icl * 190 + (r + ky) * 19 + c0]);
#pragma unroll
                for (int m = 0; m < 6; m++) xx[m] = xrow[m];
#pragma unroll
                for (int kx = 0; kx < 3; kx++) {
                    const ulonglong2* Wp = reinterpret_cast<const ulonglong2*>(
                        &Ws[icl * 576 + (ky * 3 + kx) * 64 + og * 8]);
                    ulonglong2 wa = Wp[0], wb2 = Wp[1];
                    unsigned long long w2[4] = {wa.x, wa.y, wb2.x, wb2.y};
#pragma unroll
                    for (int p = 0; p < 4; p++)
#pragma unroll
                        for (int j2 = 0; j2 < 4; j2++)
                            asm("fma.rn.f32x2 %0, %1, %2, %0;"
                                : "+l"(acc2[j2][p])
                                : "l"(w2[j2]), "l"(xx[kx + p]));
                }
            }
        }
    }

    const int y = yB + r;
#pragma unroll
    for (int j2 = 0; j2 < 4; j2++) {
        int oc0 = ocB + og * 8 + 2 * j2;
        float b0 = bias[oc0], b1 = bias[oc0 + 1];
#pragma unroll
        for (int p = 0; p < 4; p++) {
            int x = xB + c0 + p;
            if (x < FW) {
                float lo, hi;
                asm("mov.b64 {%0, %1}, %2;" : "=f"(lo), "=f"(hi) : "l"(acc2[j2][p]));
                float v0 = lo + b0;
                float v1 = hi + b1;
                g_x[oc0 * NPIX + y * FW + x] = v0 > 0.f ? v0 : 0.f;
                g_x[(oc0 + 1) * NPIX + y * FW + x] = v1 > 0.f ? v1 : 0.f;
            }
        }
    }
}

// --------------------------------------------- merged cls+reg heads ---------
// block: 256 threads = 64 pixels x 4 channel-chunks of 64. grid 625.
__global__ __launch_bounds__(256) void k_heads(const float* __restrict__ cw,
                                               const float* __restrict__ cb,
                                               const float* __restrict__ rw,
                                               const float* __restrict__ rb) {
    __shared__ float2 W2[256 * NHP];   // weights [c][h2], reused for partials [t][h2]
    __shared__ float bsm[2 * NHP];
    int t = threadIdx.x;
    for (int i = t; i < 256 * NHP; i += 256) {
        int c = i / NHP, h2 = i - NHP * c;
        int h0 = 2 * h2, h1 = h0 + 1;
        float w0 = (h0 < 9) ? cw[h0 * ICH + c] : rw[(h0 - 9) * ICH + c];
        float w1 = (h1 < 9) ? cw[h1 * ICH + c]
                            : ((h1 < NH) ? rw[(h1 - 9) * ICH + c] : 0.f);
        W2[i] = make_float2(w0, w1);
    }
    if (t < 2 * NHP) bsm[t] = (t < 9) ? cb[t] : ((t < NH) ? rb[t - 9] : 0.f);
    __syncthreads();

    int pl = t & 63;
    int ck = t >> 6;
    int p = blockIdx.x * 64 + pl;
    unsigned long long acc[NHP];
#pragma unroll
    for (int h2 = 0; h2 < NHP; h2++) {
        if (ck == 0) {
            asm("mov.b64 %0, {%1, %2};" : "=l"(acc[h2])
                : "f"(bsm[2 * h2]), "f"(bsm[2 * h2 + 1]));
        } else acc[h2] = 0ull;
    }

    int cbase = ck * 64;
    const unsigned long long* Wl = reinterpret_cast<const unsigned long long*>(W2);
#pragma unroll 2
    for (int cc = 0; cc < 64; cc++) {
        int c = cbase + cc;
        float x = g_x[c * NPIX + p];
        unsigned long long xx;
        asm("mov.b64 %0, {%1, %1};" : "=l"(xx) : "f"(x));
#pragma unroll
        for (int h2 = 0; h2 < NHP; h2++)
            asm("fma.rn.f32x2 %0, %1, %2, %0;"
                : "+l"(acc[h2]) : "l"(Wl[c * NHP + h2]), "l"(xx));
    }

    __syncthreads();                  // everyone done reading weights
    unsigned long long* Pl = reinterpret_cast<unsigned long long*>(W2);
#pragma unroll
    for (int h2 = 0; h2 < NHP; h2++) Pl[t * NHP + h2] = acc[h2];
    __syncthreads();

    if (ck == 0) {                    // t < 64, handles pixel p
        float vals[2 * NHP];
#pragma unroll
        for (int h2 = 0; h2 < NHP; h2++) {
            float2 a = W2[t * NHP + h2];
            float2 b = W2[(t + 64) * NHP + h2];
            float2 c2 = W2[(t + 128) * NHP + h2];
            float2 d = W2[(t + 192) * NHP + h2];
            vals[2 * h2]     = ((a.x + b.x) + c2.x) + d.x;
            vals[2 * h2 + 1] = ((a.y + b.y) + c2.y) + d.y;
        }
#pragma unroll
        for (int a = 0; a < 9; a++) {
            float z = vals[a], s;
            if (z >= 0.f) s = 1.f / (1.f + expf(-z));
            else { float e = expf(z); s = e / (1.f + e); }
            unsigned key = __float_as_uint(s);
            g_key[p * 9 + a] = key;
            atomicAdd(&g_hist1[key >> 16], 1u);
        }
#pragma unroll
        for (int h = 9; h < NH; h++) g_delta[(size_t)p * 36 + (h - 9)] = vals[h];
    }
}

// ---------------------------------------------- radix select: level-1 scan --
__global__ __launch_bounds__(1024) void k_scan1() {
    __shared__ unsigned cs[1024];
    int t = threadIdx.x;
    unsigned s = 0;
    for (int b = 0; b < 64; b++) s += g_hist1[t * 64 + b];
    cs[t] = s;
    __syncthreads();
    if (t == 0) {
        unsigned cum = 0; int cc = 0;
        for (int c = 1023; c >= 0; c--) {
            if (cum + cs[c] >= TOPK) { cc = c; break; }
            cum += cs[c];
        }
        unsigned B = 0;
        for (int b = cc * 64 + 63; b >= 0; b--) {
            unsigned h = g_hist1[b];
            if (cum + h >= TOPK) { B = (unsigned)b; break; }
            cum += h;
        }
        g_sel[0] = B;
        g_sel[1] = cum;
    }
}

__global__ void k_hist2() {
    int i = blockIdx.x * blockDim.x + threadIdx.x;
    if (i >= NSC) return;
    unsigned key = g_key[i];
    if ((key >> 16) == g_sel[0]) atomicAdd(&g_hist2[key & 0xFFFFu], 1u);
}

__global__ __launch_bounds__(1024) void k_scan2() {
    __shared__ unsigned cs[1024];
    int t = threadIdx.x;
    unsigned s = 0;
    for (int b = 0; b < 64; b++) s += g_hist2[t * 64 + b];
    cs[t] = s;
    __syncthreads();
    if (t == 0) {
        unsigned need = TOPK - g_sel[1];
        unsigned cum = 0; int cc = 0;
        for (int c = 1023; c >= 0; c--) {
            if (cum + cs[c] >= need) { cc = c; break; }
            cum += cs[c];
        }
        unsigned L = 0;
        for (int b = cc * 64 + 63; b >= 0; b--) {
            unsigned h = g_hist2[b];
            if (cum + h >= need) { L = (unsigned)b; break; }
            cum += h;
        }
        g_sel[2] = (g_sel[0] << 16) | L;
        g_sel[3] = g_sel[1] + cum;
    }
}

__global__ void k_gather() {
    int i = blockIdx.x * blockDim.x + threadIdx.x;
    if (i >= NSC) return;
    unsigned key = g_key[i];
    unsigned T = g_sel[2];
    if (key > T) {
        unsigned pos = atomicAdd(&g_sel[5], 1u);
        if (pos < 2048) g_candG[pos] = (unsigned)i;
    } else if (key == T) {
        unsigned pos = atomicAdd(&g_sel[6], 1u);
        if (pos < 2048) g_candE[pos] = (unsigned)i;
    }
}

// ------------------------------------------------ bitonic sort of top-K -----
__global__ __launch_bounds__(1024) void k_sort() {
    __shared__ unsigned long long S[4096];
    int t = threadIdx.x;
    unsigned cntG = min(g_sel[5], 2048u);
    unsigned cntE = min(g_sel[6], 2048u);
    unsigned tot = min(cntG + cntE, 4096u);
    for (int i = t; i < 4096; i += 1024) {
        unsigned long long v = 0ull;
        if ((unsigned)i < tot) {
            unsigned idx = ((unsigned)i < cntG) ? g_candG[i] : g_candE[i - cntG];
            v = ((unsigned long long)g_key[idx] << 32) | (unsigned)(~idx);
        }
        S[i] = v;
    }
    __syncthreads();
    for (int k2 = 2; k2 <= 4096; k2 <<= 1) {
        for (int j = k2 >> 1; j > 0; j >>= 1) {
            for (int i = t; i < 4096; i += 1024) {
                int l = i ^ j;
                if (l > i) {
                    unsigned long long A = S[i], B = S[l];
                    bool up = ((i & k2) == 0);
                    bool sw = up ? (A < B) : (A > B);
                    if (sw) { S[i] = B; S[l] = A; }
                }
            }
            __syncthreads();
        }
    }
    for (int i = t; i < TOPK; i += 1024) g_top[i] = S[i];
}

// ---------------- decode + clip + valid + stable partition (1 block) --------
__global__ __launch_bounds__(1024) void k_decode() {
    __shared__ unsigned wsum[32];
    int t = threadIdx.x;
    unsigned f[2] = {0u, 0u};
    float bxv[2][4];
    float scv[2] = {-1.f, -1.f};
#pragma unroll
    for (int k = 0; k < 2; k++) {
        int i = 2 * t + k;
        if (i < TOPK) {
            unsigned long long kv = g_top[i];
            unsigned idx = ~((unsigned)(kv & 0xFFFFFFFFull));
            int p = idx / 9, a = idx - 9 * p;
            int py = p / FW, px = p - FW * py;
            int si = a % 3, ai = a / 3;
            float scl = (si == 0) ? 128.f : ((si == 1) ? 256.f : 512.f);
            float ar  = (ai == 0) ? 0.5f  : ((ai == 1) ? 1.f : 2.f);
            float hr = sqrtf(ar);
            float wr = __fdiv_rn(1.f, hr);
            float ws = wr * scl, hs = hr * scl;
            float bx1 = rintf(-0.5f * ws), by1 = rintf(-0.5f * hs);
            float bx2 = rintf(0.5f * ws),  by2 = rintf(0.5f * hs);
            float ax = px * 8.f, ay = py * 8.f;
            float a0 = ax + bx1, a1 = ay + by1, a2 = ax + bx2, a3 = ay + by2;
            float w = a2 - a0, h = a3 - a1;
            float cx = a0 + 0.5f * w, cy = a1 + 0.5f * h;
            const float* d = &g_delta[(size_t)idx * 4];
            float dx = d[0], dy = d[1];
            float dw = fminf(d[2], BBOX_CLIP_F), dh = fminf(d[3], BBOX_CLIP_F);
            float pcx = dx * w + cx, pcy = dy * h + cy;
            float pw = expf(dw) * w, ph = expf(dh) * h;
            float x1 = pcx - 0.5f * pw, y1 = pcy - 0.5f * ph;
            float x2 = pcx + 0.5f * pw, y2 = pcy + 0.5f * ph;
            x1 = fminf(fmaxf(x1, 0.f), 1600.f);
            y1 = fminf(fmaxf(y1, 0.f), 1600.f);
            x2 = fminf(fmaxf(x2, 0.f), 1600.f);
            y2 = fminf(fmaxf(y2, 0.f), 1600.f);
            bxv[k][0] = x1; bxv[k][1] = y1; bxv[k][2] = x2; bxv[k][3] = y2;
            unsigned v = ((x2 - x1) >= 16.f) && ((y2 - y1) >= 16.f);
            f[k] = v;
            scv[k] = v ? __uint_as_float((unsigned)(kv >> 32)) : -1.f;
        }
    }
    unsigned s = f[0] + f[1];
    unsigned lane = t & 31, wid = t >> 5;
    unsigned pre = s;
    for (int o = 1; o < 32; o <<= 1) {
        unsigned v = __shfl_up_sync(0xffffffffu, pre, o);
        if (lane >= o) pre += v;
    }
    if (lane == 31) wsum[wid] = pre;
    __syncthreads();
    if (wid == 0) {
        unsigned v = wsum[lane];
        for (int o = 1; o < 32; o <<= 1) {
            unsigned u = __shfl_up_sync(0xffffffffu, v, o);
            if (lane >= o) v += u;
        }
        wsum[lane] = v;
    }
    __syncthreads();
    unsigned base = (wid > 0) ? wsum[wid - 1] : 0u;
    unsigned incl = base + pre;
    unsigned excl = incl - s;
    unsigned total = wsum[31];
#pragma unroll
    for (int k = 0; k < 2; k++) {
        int i = 2 * t + k;
        if (i < TOPK) {
            unsigned e = excl + ((k == 1) ? f[0] : 0u);
            unsigned pos = f[k] ? e : (total + ((unsigned)i - e));
            g_bx[pos * 4 + 0] = bxv[k][0];
            g_bx[pos * 4 + 1] = bxv[k][1];
            g_bx[pos * 4 + 2] = bxv[k][2];
            g_bx[pos * 4 + 3] = bxv[k][3];
            g_sc[pos] = scv[k];
        }
    }
}

// ------------------------------------------------------- NMS IoU bitmask ----
__global__ __launch_bounds__(64) void k_mask() {
    __shared__ float cb[64][4];
    int cbk = blockIdx.x, rbk = blockIdx.y;
    int cbase = cbk * 64, rbase = rbk * 64;
    int t = threadIdx.x;
    int csz = min(64, TOPK - cbase);
    if (t < csz) {
        cb[t][0] = g_bx[(cbase + t) * 4 + 0];
        cb[t][1] = g_bx[(cbase + t) * 4 + 1];
        cb[t][2] = g_bx[(cbase + t) * 4 + 2];
        cb[t][3] = g_bx[(cbase + t) * 4 + 3];
    }
    __syncthreads();
    int row = rbase + t;
    if (row >= TOPK) return;
    float rx1 = g_bx[row * 4 + 0], ry1 = g_bx[row * 4 + 1];
    float rx2 = g_bx[row * 4 + 2], ry2 = g_bx[row * 4 + 3];
    float ra = (rx2 - rx1) * (ry2 - ry1);
    unsigned long long m = 0ull;
    for (int j = 0; j < csz; j++) {
        if (cbase + j == row) continue;
        float ix1 = fmaxf(rx1, cb[j][0]), iy1 = fmaxf(ry1, cb[j][1]);
        float ix2 = fminf(rx2, cb[j][2]), iy2 = fminf(ry2, cb[j][3]);
        float iw = fmaxf(ix2 - ix1, 0.f), ih = fmaxf(iy2 - iy1, 0.f);
        float inter = iw * ih;
        float ca = (cb[j][2] - cb[j][0]) * (cb[j][3] - cb[j][1]);
        float iou = inter / (ra + ca - inter + 1e-9f);
        if (iou > 0.7f) m |= (1ull << j);
    }
    g_mask[row * 32 + cbk] = m;
}

// ----------------------------------- serial NMS reduce + emit (1 warp) ------
__global__ void k_emit(float* __restrict__ out) {
    int lane = threadIdx.x;
    unsigned long long remv = 0ull;
    unsigned long long nxt = g_mask[lane];
    int cnt = 0;
    for (int i = 0; i < TOPK; i++) {
        unsigned long long m = nxt;
        if (i + 1 < TOPK) nxt = g_mask[(size_t)(i + 1) * 32 + lane];
        int w = i >> 6, b = i & 63;
        unsigned long long rw = __shfl_sync(0xffffffffu, remv, w);
        float sc = g_sc[i];
        bool kept = (((rw >> b) & 1ull) == 0ull) && (sc > 0.f);
        if (kept) {
            remv |= m;
            if (cnt < OUTK) {
                if (lane < 4) out[cnt * 4 + lane] = g_bx[i * 4 + lane];
                if (lane == 0) out[4000 + cnt] = sc;
            }
            cnt++;
        }
    }
}

// ---------------------------------------------------------------------------
extern "C" void kernel_launch(void* const* d_in, const int* in_sizes, int n_in,
                              void* d_out, int out_size) {
    const float* feat   = (const float*)d_in[1];
    const float* conv_w = (const float*)d_in[2];
    const float* conv_b = (const float*)d_in[3];
    const float* cls_w  = (const float*)d_in[4];
    const float* cls_b  = (const float*)d_in[5];
    const float* reg_w  = (const float*)d_in[6];
    const float* reg_b  = (const float*)d_in[7];
    float* out = (float*)d_out;

    k_init<<<256, 256>>>(out);
    k_wt<<<(ICH * 9 * ICH + 255) / 256, 256>>>(conv_w);
    k_nop<<<1, 1>>>();                       // conv -> stream index 3 (profiled)
    dim3 cg(13, 25, 4);
    k_conv<<<cg, 256>>>(feat, conv_b);
    k_heads<<<NPIX / 64, 256>>>(cls_w, cls_b, reg_w, reg_b);
    k_scan1<<<1, 1024>>>();
    k_hist2<<<(NSC + 255) / 256, 256>>>();
    k_scan2<<<1, 1024>>>();
    k_gather<<<(NSC + 255) / 256, 256>>>();
    k_sort<<<1, 1024>>>();
    k_decode<<<1, 1024>>>();
    dim3 mg(32, 32);
    k_mask<<<mg, 64>>>();
    k_emit<<<1, 32>>>(out);
}

// round 16
// speedup vs baseline: 1.1149x; 1.1149x over previous
#include <cuda_runtime.h>
#include <math.h>
#include <stdint.h>

#define FH 200
#define FW 200
#define NPIX 40000
#define ICH 256
#define NA 9
#define NH 45
#define NHP 23                      // padded head pairs (46 heads, last is zero)
#define NSC 360000
#define TOPK 2000
#define OUTK 1000
#define BBOX_CLIP_F 4.135166556742356f

// conflict-free X row base: banks (rr&3)+16*((rr>>2)&1) + {0,4,8,12} tile Z32
#define XROW(rr) ((rr) * 64 + ((rr) & 3) + 16 * (((rr) >> 2) & 1))

// ---------------- persistent scratch (device globals; no allocation) --------
__device__ float g_x[ICH * NPIX];           // conv+relu output [oc][pix]
__device__ float g_wt[ICH * 9 * ICH];       // transposed conv weights [ic][tap][oc]
__device__ unsigned g_key[NSC];             // sigmoid score bits (monotone key)
__device__ float g_delta[NSC * 4];          // reg deltas [idx][4]
__device__ unsigned g_hist1[65536];
__device__ unsigned g_hist2[65536];
__device__ unsigned g_sel[8];               // 0:B 1:cntAboveB 2:T 3:cntGreater 5:ctrG 6:ctrE
__device__ unsigned g_candG[2048];
__device__ unsigned g_candE[2048];
__device__ unsigned long long g_top[TOPK];  // sorted (key<<32 | ~idx), descending
__device__ float g_bx[TOPK * 4];            // partitioned boxes (valid first)
__device__ float g_sc[TOPK];                // partitioned scores (-1 invalid)
__device__ unsigned long long g_mask[TOPK * 32];

// ---------------------------------------------------------------- init ------
__global__ void k_init(float* out) {
    int i = blockIdx.x * blockDim.x + threadIdx.x;
    if (i < 65536) { g_hist1[i] = 0u; g_hist2[i] = 0u; }
    if (i < 8) g_sel[i] = 0u;
    if (i < 5000) out[i] = 0.f;
}

// conv_w [oc][ic][ky][kx] -> g_wt [ic][tap][oc]
__global__ void k_wt(const float* __restrict__ w) {
    int i = blockIdx.x * blockDim.x + threadIdx.x;
    if (i >= ICH * 9 * ICH) return;
    int ic = i / (9 * ICH);
    int tap = (i / ICH) % 9;
    int oc = i % ICH;
    g_wt[i] = w[(oc * ICH + ic) * 9 + tap];
}

// nop: aligns k_conv to profiled stream launch index 3
__global__ void k_nop() {}

// ------------------------------------------------------------ conv 3x3 ------
// tile: 64 oc x (8 rows x 16 cols). grid (13,25,4), 256 threads.
// R10 compute ordering (j2-outer: w-operand reuse across 4 FFMA2) + scalar Xs
// with conflict-free row bases (every x LDS.32 = 1 wavefront) + alu-pipe packs.
// Bit-exact accumulation order vs rounds 10/11/14.
__global__ __launch_bounds__(256, 2) void k_conv(const float* __restrict__ feat,
                                                 const float* __restrict__ bias) {
    __shared__ float Ws[8 * 9 * 64];     // [icl][tap][oc']  18432 B
    __shared__ float Xs[8 * 640];        // [icl][rowbase(rr) + cc]  20480 B

    const int tid = threadIdx.x;
    const int og = tid >> 5;             // warp id -> oc sub-group (8 oc)
    const int pg = tid & 31;
    const int r  = pg >> 2;              // row in tile 0..7
    const int c0 = (pg & 3) << 2;        // col base 0,4,8,12
    const int xB = blockIdx.x * 16;
    const int yB = blockIdx.y * 8;
    const int ocB = blockIdx.z * 64;

    unsigned long long acc2[4][4];       // [oc-pair j2][pixel p]
#pragma unroll
    for (int j2 = 0; j2 < 4; j2++)
#pragma unroll
        for (int p = 0; p < 4; p++) acc2[j2][p] = 0ull;

    // ---- prefetch addressing ----
    const int wbase = (tid >> 6) * 256 + ocB + (tid & 63);  // + ch*18432 + k*1024
    int xGOff[6], xSOff[6];
    unsigned okm = 0u;                   // bit k: in-bounds (load), write always if in-range
#pragma unroll
    for (int k = 0; k < 6; k++) {
        int i = tid + k * 256;
        bool xin = (i < 1440);
        int icl = i / 180;
        int rem = i - icl * 180;
        int rr = rem / 18;
        int cc = rem - rr * 18;
        int gy = yB - 1 + rr;
        int gx = xB - 1 + cc;
        bool inb = xin && gy >= 0 && gy < FH && gx >= 0 && gx < FW;
        if (inb) okm |= (1u << k);
        xGOff[k] = inb ? (icl * NPIX + gy * FW + gx) : 0;
        xSOff[k] = xin ? (icl * 640 + XROW(rr) + cc) : 0;
    }
    const bool xin5 = (tid < 1440 - 5 * 256);

    float wbuf[18], xbuf[6];
#pragma unroll
    for (int k = 0; k < 18; k++) wbuf[k] = g_wt[wbase + k * 1024];
#pragma unroll
    for (int k = 0; k < 6; k++) xbuf[k] = (okm >> k & 1u) ? feat[xGOff[k]] : 0.f;

    for (int ch = 0; ch < 32; ch++) {
        __syncthreads();
#pragma unroll
        for (int k = 0; k < 18; k++) Ws[tid + k * 256] = wbuf[k];
#pragma unroll
        for (int k = 0; k < 6; k++)
            if (k < 5 || xin5) Xs[xSOff[k]] = xbuf[k];
        __syncthreads();
        if (ch < 31) {
            const int wb = (ch + 1) * (8 * 9 * ICH) + wbase;
            const int xb = (ch + 1) * (8 * NPIX);
#pragma unroll
            for (int k = 0; k < 18; k++) wbuf[k] = g_wt[wb + k * 1024];
#pragma unroll
            for (int k = 0; k < 6; k++)
                xbuf[k] = (okm >> k & 1u) ? feat[xGOff[k] + xb] : 0.f;
        }

#pragma unroll
        for (int icl = 0; icl < 8; icl++) {
#pragma unroll
            for (int ky = 0; ky < 3; ky++) {
                const float* xrow = &Xs[icl * 640 + XROW(r + ky) + c0];
                float xr[6];
#pragma unroll
                for (int m = 0; m < 6; m++) xr[m] = xrow[m];
                unsigned long long xx[6];
#pragma unroll
                for (int m = 0; m < 6; m++)
                    asm("mov.b64 %0, {%1, %1};" : "=l"(xx[m]) : "f"(xr[m]));
#pragma unroll
                for (int kx = 0; kx < 3; kx++) {
                    const unsigned long long* Wp = reinterpret_cast<const unsigned long long*>(
                        &Ws[icl * 576 + (ky * 3 + kx) * 64 + og * 8]);
                    unsigned long long w2[4];
#pragma unroll
                    for (int j2 = 0; j2 < 4; j2++) w2[j2] = Wp[j2];
#pragma unroll
                    for (int j2 = 0; j2 < 4; j2++)
#pragma unroll
                        for (int p = 0; p < 4; p++)
                            asm("fma.rn.f32x2 %0, %1, %2, %0;"
                                : "+l"(acc2[j2][p])
                                : "l"(w2[j2]), "l"(xx[kx + p]));
                }
            }
        }
    }

    const int y = yB + r;
#pragma unroll
    for (int j2 = 0; j2 < 4; j2++) {
        int oc0 = ocB + og * 8 + 2 * j2;
        float b0 = bias[oc0], b1 = bias[oc0 + 1];
#pragma unroll
        for (int p = 0; p < 4; p++) {
            int x = xB + c0 + p;
            if (x < FW) {
                float lo, hi;
                asm("mov.b64 {%0, %1}, %2;" : "=f"(lo), "=f"(hi) : "l"(acc2[j2][p]));
                float v0 = lo + b0;
                float v1 = hi + b1;
                g_x[oc0 * NPIX + y * FW + x] = v0 > 0.f ? v0 : 0.f;
                g_x[(oc0 + 1) * NPIX + y * FW + x] = v1 > 0.f ? v1 : 0.f;
            }
        }
    }
}

// --------------------------------------------- merged cls+reg heads ---------
// block: 256 threads = 64 pixels x 4 channel-chunks of 64. grid 625.
__global__ __launch_bounds__(256) void k_heads(const float* __restrict__ cw,
                                               const float* __restrict__ cb,
                                               const float* __restrict__ rw,
                                               const float* __restrict__ rb) {
    __shared__ float2 W2[256 * NHP];   // weights [c][h2], reused for partials [t][h2]
    __shared__ float bsm[2 * NHP];
    int t = threadIdx.x;
    for (int i = t; i < 256 * NHP; i += 256) {
        int c = i / NHP, h2 = i - NHP * c;
        int h0 = 2 * h2, h1 = h0 + 1;
        float w0 = (h0 < 9) ? cw[h0 * ICH + c] : rw[(h0 - 9) * ICH + c];
        float w1 = (h1 < 9) ? cw[h1 * ICH + c]
                            : ((h1 < NH) ? rw[(h1 - 9) * ICH + c] : 0.f);
        W2[i] = make_float2(w0, w1);
    }
    if (t < 2 * NHP) bsm[t] = (t < 9) ? cb[t] : ((t < NH) ? rb[t - 9] : 0.f);
    __syncthreads();

    int pl = t & 63;
    int ck = t >> 6;
    int p = blockIdx.x * 64 + pl;
    unsigned long long acc[NHP];
#pragma unroll
    for (int h2 = 0; h2 < NHP; h2++) {
        if (ck == 0) {
            asm("mov.b64 %0, {%1, %2};" : "=l"(acc[h2])
                : "f"(bsm[2 * h2]), "f"(bsm[2 * h2 + 1]));
        } else acc[h2] = 0ull;
    }

    int cbase = ck * 64;
    const unsigned long long* Wl = reinterpret_cast<const unsigned long long*>(W2);
#pragma unroll 2
    for (int cc = 0; cc < 64; cc++) {
        int c = cbase + cc;
        float x = g_x[c * NPIX + p];
        unsigned long long xx;
        asm("mov.b64 %0, {%1, %1};" : "=l"(xx) : "f"(x));
#pragma unroll
        for (int h2 = 0; h2 < NHP; h2++)
            asm("fma.rn.f32x2 %0, %1, %2, %0;"
                : "+l"(acc[h2]) : "l"(Wl[c * NHP + h2]), "l"(xx));
    }

    __syncthreads();                  // everyone done reading weights
    unsigned long long* Pl = reinterpret_cast<unsigned long long*>(W2);
#pragma unroll
    for (int h2 = 0; h2 < NHP; h2++) Pl[t * NHP + h2] = acc[h2];
    __syncthreads();

    if (ck == 0) {                    // t < 64, handles pixel p
        float vals[2 * NHP];
#pragma unroll
        for (int h2 = 0; h2 < NHP; h2++) {
            float2 a = W2[t * NHP + h2];
            float2 b = W2[(t + 64) * NHP + h2];
            float2 c2 = W2[(t + 128) * NHP + h2];
            float2 d = W2[(t + 192) * NHP + h2];
            vals[2 * h2]     = ((a.x + b.x) + c2.x) + d.x;
            vals[2 * h2 + 1] = ((a.y + b.y) + c2.y) + d.y;
        }
#pragma unroll
        for (int a = 0; a < 9; a++) {
            float z = vals[a], s;
            if (z >= 0.f) s = 1.f / (1.f + expf(-z));
            else { float e = expf(z); s = e / (1.f + e); }
            unsigned key = __float_as_uint(s);
            g_key[p * 9 + a] = key;
            atomicAdd(&g_hist1[key >> 16], 1u);
        }
#pragma unroll
        for (int h = 9; h < NH; h++) g_delta[(size_t)p * 36 + (h - 9)] = vals[h];
    }
}

// ---------------------------------------------- radix select: level-1 scan --
__global__ __launch_bounds__(1024) void k_scan1() {
    __shared__ unsigned cs[1024];
    int t = threadIdx.x;
    unsigned s = 0;
    for (int b = 0; b < 64; b++) s += g_hist1[t * 64 + b];
    cs[t] = s;
    __syncthreads();
    if (t == 0) {
        unsigned cum = 0; int cc = 0;
        for (int c = 1023; c >= 0; c--) {
            if (cum + cs[c] >= TOPK) { cc = c; break; }
            cum += cs[c];
        }
        unsigned B = 0;
        for (int b = cc * 64 + 63; b >= 0; b--) {
            unsigned h = g_hist1[b];
            if (cum + h >= TOPK) { B = (unsigned)b; break; }
            cum += h;
        }
        g_sel[0] = B;
        g_sel[1] = cum;
    }
}

__global__ void k_hist2() {
    int i = blockIdx.x * blockDim.x + threadIdx.x;
    if (i >= NSC) return;
    unsigned key = g_key[i];
    if ((key >> 16) == g_sel[0]) atomicAdd(&g_hist2[key & 0xFFFFu], 1u);
}

__global__ __launch_bounds__(1024) void k_scan2() {
    __shared__ unsigned cs[1024];
    int t = threadIdx.x;
    unsigned s = 0;
    for (int b = 0; b < 64; b++) s += g_hist2[t * 64 + b];
    cs[t] = s;
    __syncthreads();
    if (t == 0) {
        unsigned need = TOPK - g_sel[1];
        unsigned cum = 0; int cc = 0;
        for (int c = 1023; c >= 0; c--) {
            if (cum + cs[c] >= need) { cc = c; break; }
            cum += cs[c];
        }
        unsigned L = 0;
        for (int b = cc * 64 + 63; b >= 0; b--) {
            unsigned h = g_hist2[b];
            if (cum + h >= need) { L = (unsigned)b; break; }
            cum += h;
        }
        g_sel[2] = (g_sel[0] << 16) | L;
        g_sel[3] = g_sel[1] + cum;
    }
}

__global__ void k_gather() {
    int i = blockIdx.x * blockDim.x + threadIdx.x;
    if (i >= NSC) return;
    unsigned key = g_key[i];
    unsigned T = g_sel[2];
    if (key > T) {
        unsigned pos = atomicAdd(&g_sel[5], 1u);
        if (pos < 2048) g_candG[pos] = (unsigned)i;
    } else if (key == T) {
        unsigned pos = atomicAdd(&g_sel[6], 1u);
        if (pos < 2048) g_candE[pos] = (unsigned)i;
    }
}

// ------------------------------------------------ bitonic sort of top-K -----
__global__ __launch_bounds__(1024) void k_sort() {
    __shared__ unsigned long long S[4096];
    int t = threadIdx.x;
    unsigned cntG = min(g_sel[5], 2048u);
    unsigned cntE = min(g_sel[6], 2048u);
    unsigned tot = min(cntG + cntE, 4096u);
    for (int i = t; i < 4096; i += 1024) {
        unsigned long long v = 0ull;
        if ((unsigned)i < tot) {
            unsigned idx = ((unsigned)i < cntG) ? g_candG[i] : g_candE[i - cntG];
            v = ((unsigned long long)g_key[idx] << 32) | (unsigned)(~idx);
        }
        S[i] = v;
    }
    __syncthreads();
    for (int k2 = 2; k2 <= 4096; k2 <<= 1) {
        for (int j = k2 >> 1; j > 0; j >>= 1) {
            for (int i = t; i < 4096; i += 1024) {
                int l = i ^ j;
                if (l > i) {
                    unsigned long long A = S[i], B = S[l];
                    bool up = ((i & k2) == 0);
                    bool sw = up ? (A < B) : (A > B);
                    if (sw) { S[i] = B; S[l] = A; }
                }
            }
            __syncthreads();
        }
    }
    for (int i = t; i < TOPK; i += 1024) g_top[i] = S[i];
}

// ---------------- decode + clip + valid + stable partition (1 block) --------
__global__ __launch_bounds__(1024) void k_decode() {
    __shared__ unsigned wsum[32];
    int t = threadIdx.x;
    unsigned f[2] = {0u, 0u};
    float bxv[2][4];
    float scv[2] = {-1.f, -1.f};
#pragma unroll
    for (int k = 0; k < 2; k++) {
        int i = 2 * t + k;
        if (i < TOPK) {
            unsigned long long kv = g_top[i];
            unsigned idx = ~((unsigned)(kv & 0xFFFFFFFFull));
            int p = idx / 9, a = idx - 9 * p;
            int py = p / FW, px = p - FW * py;
            int si = a % 3, ai = a / 3;
            float scl = (si == 0) ? 128.f : ((si == 1) ? 256.f : 512.f);
            float ar  = (ai == 0) ? 0.5f  : ((ai == 1) ? 1.f : 2.f);
            float hr = sqrtf(ar);
            float wr = __fdiv_rn(1.f, hr);
            float ws = wr * scl, hs = hr * scl;
            float bx1 = rintf(-0.5f * ws), by1 = rintf(-0.5f * hs);
            float bx2 = rintf(0.5f * ws),  by2 = rintf(0.5f * hs);
            float ax = px * 8.f, ay = py * 8.f;
            float a0 = ax + bx1, a1 = ay + by1, a2 = ax + bx2, a3 = ay + by2;
            float w = a2 - a0, h = a3 - a1;
            float cx = a0 + 0.5f * w, cy = a1 + 0.5f * h;
            const float* d = &g_delta[(size_t)idx * 4];
            float dx = d[0], dy = d[1];
            float dw = fminf(d[2], BBOX_CLIP_F), dh = fminf(d[3], BBOX_CLIP_F);
            float pcx = dx * w + cx, pcy = dy * h + cy;
            float pw = expf(dw) * w, ph = expf(dh) * h;
            float x1 = pcx - 0.5f * pw, y1 = pcy - 0.5f * ph;
            float x2 = pcx + 0.5f * pw, y2 = pcy + 0.5f * ph;
            x1 = fminf(fmaxf(x1, 0.f), 1600.f);
            y1 = fminf(fmaxf(y1, 0.f), 1600.f);
            x2 = fminf(fmaxf(x2, 0.f), 1600.f);
            y2 = fminf(fmaxf(y2, 0.f), 1600.f);
            bxv[k][0] = x1; bxv[k][1] = y1; bxv[k][2] = x2; bxv[k][3] = y2;
            unsigned v = ((x2 - x1) >= 16.f) && ((y2 - y1) >= 16.f);
            f[k] = v;
            scv[k] = v ? __uint_as_float((unsigned)(kv >> 32)) : -1.f;
        }
    }
    unsigned s = f[0] + f[1];
    unsigned lane = t & 31, wid = t >> 5;
    unsigned pre = s;
    for (int o = 1; o < 32; o <<= 1) {
        unsigned v = __shfl_up_sync(0xffffffffu, pre, o);
        if (lane >= o) pre += v;
    }
    if (lane == 31) wsum[wid] = pre;
    __syncthreads();
    if (wid == 0) {
        unsigned v = wsum[lane];
        for (int o = 1; o < 32; o <<= 1) {
            unsigned u = __shfl_up_sync(0xffffffffu, v, o);
            if (lane >= o) v += u;
        }
        wsum[lane] = v;
    }
    __syncthreads();
    unsigned base = (wid > 0) ? wsum[wid - 1] : 0u;
    unsigned incl = base + pre;
    unsigned excl = incl - s;
    unsigned total = wsum[31];
#pragma unroll
    for (int k = 0; k < 2; k++) {
        int i = 2 * t + k;
        if (i < TOPK) {
            unsigned e = excl + ((k == 1) ? f[0] : 0u);
            unsigned pos = f[k] ? e : (total + ((unsigned)i - e));
            g_bx[pos * 4 + 0] = bxv[k][0];
            g_bx[pos * 4 + 1] = bxv[k][1];
            g_bx[pos * 4 + 2] = bxv[k][2];
            g_bx[pos * 4 + 3] = bxv[k][3];
            g_sc[pos] = scv[k];
        }
    }
}

// ------------------------------------------------------- NMS IoU bitmask ----
__global__ __launch_bounds__(64) void k_mask() {
    __shared__ float cb[64][4];
    int cbk = blockIdx.x, rbk = blockIdx.y;
    int cbase = cbk * 64, rbase = rbk * 64;
    int t = threadIdx.x;
    int csz = min(64, TOPK - cbase);
    if (t < csz) {
        cb[t][0] = g_bx[(cbase + t) * 4 + 0];
        cb[t][1] = g_bx[(cbase + t) * 4 + 1];
        cb[t][2] = g_bx[(cbase + t) * 4 + 2];
        cb[t][3] = g_bx[(cbase + t) * 4 + 3];
    }
    __syncthreads();
    int row = rbase + t;
    if (row >= TOPK) return;
    float rx1 = g_bx[row * 4 + 0], ry1 = g_bx[row * 4 + 1];
    float rx2 = g_bx[row * 4 + 2], ry2 = g_bx[row * 4 + 3];
    float ra = (rx2 - rx1) * (ry2 - ry1);
    unsigned long long m = 0ull;
    for (int j = 0; j < csz; j++) {
        if (cbase + j == row) continue;
        float ix1 = fmaxf(rx1, cb[j][0]), iy1 = fmaxf(ry1, cb[j][1]);
        float ix2 = fminf(rx2, cb[j][2]), iy2 = fminf(ry2, cb[j][3]);
        float iw = fmaxf(ix2 - ix1, 0.f), ih = fmaxf(iy2 - iy1, 0.f);
        float inter = iw * ih;
        float ca = (cb[j][2] - cb[j][0]) * (cb[j][3] - cb[j][1]);
        float iou = inter / (ra + ca - inter + 1e-9f);
        if (iou > 0.7f) m |= (1ull << j);
    }
    g_mask[row * 32 + cbk] = m;
}

// ----------------------------------- serial NMS reduce + emit (1 warp) ------
__global__ void k_emit(float* __restrict__ out) {
    int lane = threadIdx.x;
    unsigned long long remv = 0ull;
    unsigned long long nxt = g_mask[lane];
    int cnt = 0;
    for (int i = 0; i < TOPK; i++) {
        unsigned long long m = nxt;
        if (i + 1 < TOPK) nxt = g_mask[(size_t)(i + 1) * 32 + lane];
        int w = i >> 6, b = i & 63;
        unsigned long long rw = __shfl_sync(0xffffffffu, remv, w);
        float sc = g_sc[i];
        bool kept = (((rw >> b) & 1ull) == 0ull) && (sc > 0.f);
        if (kept) {
            remv |= m;
            if (cnt < OUTK) {
                if (lane < 4) out[cnt * 4 + lane] = g_bx[i * 4 + lane];
                if (lane == 0) out[4000 + cnt] = sc;
            }
            cnt++;
        }
    }
}

// ---------------------------------------------------------------------------
extern "C" void kernel_launch(void* const* d_in, const int* in_sizes, int n_in,
                              void* d_out, int out_size) {
    const float* feat   = (const float*)d_in[1];
    const float* conv_w = (const float*)d_in[2];
    const float* conv_b = (const float*)d_in[3];
    const float* cls_w  = (const float*)d_in[4];
    const float* cls_b  = (const float*)d_in[5];
    const float* reg_w  = (const float*)d_in[6];
    const float* reg_b  = (const float*)d_in[7];
    float* out = (float*)d_out;

    k_init<<<256, 256>>>(out);
    k_wt<<<(ICH * 9 * ICH + 255) / 256, 256>>>(conv_w);
    k_nop<<<1, 1>>>();                       // conv -> stream index 3 (profiled)
    dim3 cg(13, 25, 4);
    k_conv<<<cg, 256>>>(feat, conv_b);
    k_heads<<<NPIX / 64, 256>>>(cls_w, cls_b, reg_w, reg_b);
    k_scan1<<<1, 1024>>>();
    k_hist2<<<(NSC + 255) / 256, 256>>>();
    k_scan2<<<1, 1024>>>();
    k_gather<<<(NSC + 255) / 256, 256>>>();
    k_sort<<<1, 1024>>>();
    k_decode<<<1, 1024>>>();
    dim3 mg(32, 32);
    k_mask<<<mg, 64>>>();
    k_emit<<<1, 32>>>(out);
}